// round 15
// baseline (speedup 1.0000x reference)
#include <cuda_runtime.h>
#include <cstdint>

#define B_  4
#define S_  2048
#define D_  1024
#define H_  16
#define DK_ 64

#define QKV_Z ((size_t)B_*H_*DK_*S_)   // floats per z-slab

// Scratch (device globals). MUST only be referenced from device code:
// host-side references give the host shadow address, which GB300 ATS
// silently dereferences (round-3/4 bug).
__device__ float g_QKV[3*QKV_Z];              // z0: Q [B,H,S,dk] (tf32, pre-scaled 0.125*log2e); z1: K [B,H,S,dk] (tf32); z2: V [B,H,dv,S] (tf32)
__device__ float g_X[(size_t)B_*S_*D_];       // concat-heads attention output (tf32-rounded)
__device__ float g_embT[(size_t)B_*S_*D_];    // emb pre-converted to tf32
__device__ float g_Wall[(size_t)3*H_*DK_*D_]; // [3072][1024] K-major fused QKV weights (tf32)
__device__ float g_Wot[(size_t)D_*D_];        // [1024][1024] K-major output weights (tf32)

// ============================ helpers ======================================
__device__ __forceinline__ uint32_t f2tf32(float x) {
    uint32_t u;
    asm("cvt.rna.tf32.f32 %0, %1;" : "=r"(u) : "f"(x));
    return u;
}
__device__ __forceinline__ void mma8(float* d, const uint32_t* a, const uint32_t* b) {
    asm volatile(
        "mma.sync.aligned.m16n8k8.row.col.f32.tf32.tf32.f32 "
        "{%0,%1,%2,%3}, {%4,%5,%6,%7}, {%8,%9}, {%0,%1,%2,%3};"
        : "+f"(d[0]), "+f"(d[1]), "+f"(d[2]), "+f"(d[3])
        : "r"(a[0]), "r"(a[1]), "r"(a[2]), "r"(a[3]), "r"(b[0]), "r"(b[1]));
}
__device__ __forceinline__ uint32_t smem_u32(const void* p) {
    uint32_t a;
    asm("{ .reg .u64 t; cvta.to.shared.u64 t, %1; cvt.u32.u64 %0, t; }"
        : "=r"(a) : "l"(p));
    return a;
}
#define CP16(d, s) \
    asm volatile("cp.async.cg.shared.global [%0], [%1], 16;" :: "r"(d), "l"(s))
#define CP_COMMIT() asm volatile("cp.async.commit_group;" ::: "memory")
#define CP_WAIT0()  asm volatile("cp.async.wait_group 0;" ::: "memory")
#define LDSM4(r0, r1, r2, r3, addr) \
    asm volatile("ldmatrix.sync.aligned.m8n8.x4.shared.b16 {%0,%1,%2,%3}, [%4];" \
        : "=r"(r0), "=r"(r1), "=r"(r2), "=r"(r3) : "r"(addr))

// ====================== emb fp32 -> tf32 pre-convert =======================
__global__ __launch_bounds__(256) void cvt_kernel(const float* __restrict__ src)
{
    size_t i = ((size_t)blockIdx.x * 256 + threadIdx.x) * 4;
    float4 v = __ldg((const float4*)(src + i));
    uint4 o = make_uint4(f2tf32(v.x), f2tf32(v.y), f2tf32(v.z), f2tf32(v.w));
    *(uint4*)((uint32_t*)g_embT + i) = o;
}

// ====================== weight transposes (tiny, pre-convert tf32) ========
__global__ __launch_bounds__(256) void wtrans_kernel(
    const float* __restrict__ Wq, const float* __restrict__ Wk,
    const float* __restrict__ Wv)
{
    __shared__ float t[64][65];
    const int dt = blockIdx.x, h = blockIdx.y, z = blockIdx.z;
    const float* W = (z == 0 ? Wq : (z == 1 ? Wk : Wv)) + (size_t)h * D_ * DK_;
    const int d0 = dt * 64;
#pragma unroll
    for (int i = 0; i < 16; i++) {
        int idx = threadIdx.x + i * 256;
        int r = idx >> 6, c = idx & 63;
        t[c][r] = W[(size_t)(d0 + r) * DK_ + c];
    }
    __syncthreads();
#pragma unroll
    for (int i = 0; i < 16; i++) {
        int idx = threadIdx.x + i * 256;
        int r = idx >> 6, c = idx & 63;
        g_Wall[(size_t)(z * 1024 + h * 64 + r) * D_ + d0 + c] =
            __uint_as_float(f2tf32(t[r][c]));
    }
}

__global__ __launch_bounds__(256) void wot_kernel(const float* __restrict__ Wo)
{
    __shared__ float t[64][65];
    const int kt = blockIdx.x, nt = blockIdx.y;
    const int k0 = kt * 64, n0 = nt * 64;
#pragma unroll
    for (int i = 0; i < 16; i++) {
        int idx = threadIdx.x + i * 256;
        int r = idx >> 6, c = idx & 63;
        t[c][r] = Wo[(size_t)(k0 + r) * D_ + n0 + c];
    }
    __syncthreads();
#pragma unroll
    for (int i = 0; i < 16; i++) {
        int idx = threadIdx.x + i * 256;
        int r = idx >> 6, c = idx & 63;
        g_Wot[(size_t)(n0 + r) * D_ + k0 + c] = __uint_as_float(f2tf32(t[r][c]));
    }
}

// =============== HMMA tf32 GEMM: C[M,N] = A[M,K] * B[N,K]^T ================
// Both operands pre-converted tf32 in gmem -> raw cp.async; fragments via
// ldmatrix.x4. 128x128 CTA tile, 8 warps 4(M)x2(N), KC=32, double buffered.
// SINGLE barrier per chunk, flash-style: wait chunk c -> sync -> issue c+1
// -> compute c (copy c+1 overlaps compute c; wait deferred to next iter top).
// __launch_bounds__(256,2): cap regs at 128 so 2 CTAs/SM fit.
#define MMLDA 36
#define MM_SMEM_BYTES 73728

__global__ __launch_bounds__(256, 2) void mm_kernel(
    const float* __restrict__ bias, float* __restrict__ Cout, int mode)
{
    extern __shared__ __align__(16) uint32_t smu[];
    const uint32_t sb = smem_u32(smu);
    const uint32_t Asa[2] = { sb,               sb + 9216u * 4u };
    const uint32_t Bofs = 4608u * 4u;

    const float* A  = (mode == 0) ? g_embT : g_X;
    const float* Bm = (mode == 0) ? g_Wall : g_Wot;

    const int tid = threadIdx.x;
    const int m0 = blockIdx.x * 128, n0 = blockIdx.y * 128;
    const int w = tid >> 5, lane = tid & 31;
    const int wm = w & 3, wn = w >> 2;
    const int g = lane >> 2, t = lane & 3;

    float acc[2][8][4];
#pragma unroll
    for (int mi = 0; mi < 2; mi++)
#pragma unroll
        for (int ni = 0; ni < 8; ni++)
#pragma unroll
            for (int r = 0; r < 4; r++) acc[mi][ni][r] = 0.f;

    // cp.async coords: 128 rows x 128B; 4 chunks per thread per operand
    const int ldr = tid >> 3, ldc = tid & 7;
    const uint32_t dsto = (uint32_t)(ldr * MMLDA + ldc * 4) * 4u;

    // ldmatrix lane addressing (A-fragment order): row=(l&7)+((l>>3)&1)*8, col=((l>>4)&1)*4
    const uint32_t laneA = (uint32_t)((((lane & 7) + ((lane >> 3) & 1) * 8) * MMLDA
                                       + ((lane >> 4) & 1) * 4) * 4);
    // B-fragment order: row=((l>>4)&1)*8+(l&7), col=((l>>3)&1)*4
    const uint32_t laneB = (uint32_t)(((((lane >> 4) & 1) * 8 + (lane & 7)) * MMLDA
                                       + ((lane >> 3) & 1) * 4) * 4);

#define MM_ISSUE(stagebase, k0n) do {                                          \
    _Pragma("unroll")                                                          \
    for (int _i = 0; _i < 4; _i++) {                                           \
        CP16((stagebase) + dsto + (uint32_t)(_i * 32 * MMLDA * 4),             \
             A  + (size_t)(m0 + ldr + _i * 32) * D_ + (k0n) + ldc * 4);        \
        CP16((stagebase) + Bofs + dsto + (uint32_t)(_i * 32 * MMLDA * 4),      \
             Bm + (size_t)(n0 + ldr + _i * 32) * D_ + (k0n) + ldc * 4);        \
    }                                                                          \
    CP_COMMIT();                                                               \
} while (0)

    // prologue: chunk 0 in flight
    MM_ISSUE(Asa[0], 0);

    for (int c = 0; c < 32; c++) {
        const int cur = c & 1;
        CP_WAIT0();          // chunk c arrived
        __syncthreads();     // all warps done reading buffer cur^1 (iter c-1)
        if (c + 1 < 32)
            MM_ISSUE(Asa[cur ^ 1], (c + 1) * 32);   // overlaps compute below
        const uint32_t abase = Asa[cur] + laneA + (uint32_t)(wm * 32 * MMLDA * 4);
        const uint32_t bbase = Asa[cur] + Bofs + laneB + (uint32_t)(wn * 64 * MMLDA * 4);
#pragma unroll
        for (int ks = 0; ks < 4; ks++) {
            uint32_t a0[4], a1[4];
            LDSM4(a0[0], a0[1], a0[2], a0[3], abase + (uint32_t)(ks * 32));
            LDSM4(a1[0], a1[1], a1[2], a1[3],
                  abase + (uint32_t)(16 * MMLDA * 4 + ks * 32));
#pragma unroll
            for (int nn = 0; nn < 8; nn += 2) {
                uint32_t bf[4];
                LDSM4(bf[0], bf[1], bf[2], bf[3],
                      bbase + (uint32_t)(nn * 8 * MMLDA * 4 + ks * 32));
                mma8(acc[0][nn],     a0, bf);
                mma8(acc[0][nn + 1], a0, bf + 2);
                mma8(acc[1][nn],     a1, bf);
                mma8(acc[1][nn + 1], a1, bf + 2);
            }
        }
        // no end-of-loop wait/barrier: next iteration's top protects buffers
    }
#undef MM_ISSUE
    __syncthreads();   // protect epilogue smem reuse (mode 0, z==2)

    // ---------------- epilogue ----------------
    if (mode == 0) {
        const int z = n0 >> 10;
        const int bidx = m0 >> 11, s0 = m0 & 2047;
        if (z == 2) {
            // V: k-major [B,H,dv,S] via SMEM transpose
            float* smf = (float*)smu;           // [col][row], ld=132
#pragma unroll
            for (int mi = 0; mi < 2; mi++)
#pragma unroll
                for (int ni = 0; ni < 8; ni++) {
                    int r = wm * 32 + mi * 16 + g;
                    int cc = wn * 64 + ni * 8 + 2 * t;
                    smf[cc * 132 + r]           = acc[mi][ni][0];
                    smf[(cc + 1) * 132 + r]     = acc[mi][ni][1];
                    smf[cc * 132 + r + 8]       = acc[mi][ni][2];
                    smf[(cc + 1) * 132 + r + 8] = acc[mi][ni][3];
                }
            __syncthreads();
            float* vbase = g_QKV + 2 * QKV_Z;
#pragma unroll
            for (int ccc = 0; ccc < 16; ccc++) {
                int col = w + ccc * 8;
                int nglob = n0 + col;
                int h = (nglob >> 6) & 15, kb = nglob & 63;
                float* dst = vbase + ((size_t)(bidx * 16 + h) * 64 + kb) * 2048 + s0;
#pragma unroll
                for (int rr = 0; rr < 4; rr++)
                    dst[rr * 32 + lane] =
                        __uint_as_float(f2tf32(smf[col * 132 + rr * 32 + lane]));
            }
        } else {
            // Q (z=0, pre-scale 0.125*log2e) and K (z=1): row-major [B,H,S,dk]
            const float qsc = (z == 0) ? 0.125f * 1.4426950408889634f : 1.0f;
            float* zbase = g_QKV + (size_t)z * QKV_Z;
#pragma unroll
            for (int mi = 0; mi < 2; mi++)
#pragma unroll
                for (int ni = 0; ni < 8; ni++) {
                    int r = m0 + wm * 32 + mi * 16 + g;
                    int s = r & 2047;
                    int n = n0 + wn * 64 + ni * 8 + 2 * t;
                    int h = (n >> 6) & 15, kb = n & 63;
                    float* dst = zbase + ((size_t)(bidx * 16 + h) * 2048 + s) * 64 + kb;
                    *(float2*)dst = make_float2(
                        __uint_as_float(f2tf32(qsc * acc[mi][ni][0])),
                        __uint_as_float(f2tf32(qsc * acc[mi][ni][1])));
                    *(float2*)(dst + 8 * 64) = make_float2(
                        __uint_as_float(f2tf32(qsc * acc[mi][ni][2])),
                        __uint_as_float(f2tf32(qsc * acc[mi][ni][3])));
                }
        }
    } else {
#pragma unroll
        for (int mi = 0; mi < 2; mi++)
#pragma unroll
            for (int ni = 0; ni < 8; ni++) {
                int m = m0 + wm * 32 + mi * 16 + g;
                int n = n0 + wn * 64 + ni * 8 + 2 * t;
                float2 bv = *(const float2*)(bias + n);
                *(float2*)(Cout + (size_t)m * D_ + n) =
                    make_float2(acc[mi][ni][0] + bv.x, acc[mi][ni][1] + bv.y);
                *(float2*)(Cout + (size_t)(m + 8) * D_ + n) =
                    make_float2(acc[mi][ni][2] + bv.x, acc[mi][ni][3] + bv.y);
            }
    }
}

// ================ Flash attention on HMMA tf32, causal =====================
// BQ=128, BK=64, 256 threads; warp wq owns q-rows [wq*16, wq*16+16).
// Q resident in registers; K smem [kv][dk], V smem [dv][kv] (ld=68,
// LDSM-conflict-free); B-frags via ldmatrix.x4; P through per-warp smem.
// SINGLE __syncthreads per tile (round-14 structure).
#define FL_KS0b 0
#define FL_KS1b 17408
#define FL_VS0b 34816
#define FL_VS1b 52224
#define FL_Pb   69632
#define FL_SMEM_BYTES 102400

__global__ __launch_bounds__(256, 2) void flash_kernel()
{
    extern __shared__ __align__(16) uint32_t smu[];
    const uint32_t sb = smem_u32(smu);
    const uint32_t ksa[2] = { sb + FL_KS0b, sb + FL_KS1b };
    const uint32_t vsa[2] = { sb + FL_VS0b, sb + FL_VS1b };

    const int qt = (int)gridDim.x - 1 - (int)blockIdx.x;  // heavy tiles first
    const int h = blockIdx.y, b = blockIdx.z;
    const int bh = b * H_ + h;
    const float* Qb = g_QKV + (size_t)bh * S_ * 64;             // [S][dk]
    const float* Kb = g_QKV + QKV_Z + (size_t)bh * S_ * 64;     // [S][dk]
    const float* Vb = g_QKV + 2 * QKV_Z + (size_t)bh * 64 * S_; // [dv][S]
    const int q0 = qt * 128;
    const int tid = threadIdx.x;
    const int wq = tid >> 5, lane = tid & 31;
    const int g = lane >> 2, t = lane & 3;
    const int qb = wq * 16;

    // ldmatrix B-frag lane addressing (shared by K and V tiles, ld=68 words)
    const int lrow8 = lane & 7;
    const int lsel  = ((lane >> 3) & 1) * 4;
    const int lblk  = (lane >> 4) & 1;
    const uint32_t laneKV = (uint32_t)(((lblk * 8 + lrow8) * 68 + lsel) * 4);

    // P fragment buffer: per-warp 1024 words, A-fragment order, XOR swizzle
    uint32_t* Pfw = smu + FL_Pb / 4 + wq * 1024;
    const int x2a = 2 * t, x2b = 2 * t + 1;
    const int l2a = 4 * g + (x2a & 3), l2b = 4 * g + (x2b & 3);
    const int offa = (l2a ^ (l2a >> 2)) * 4 + ((x2a >> 2) << 1);
    const int offb = (l2b ^ (l2b >> 2)) * 4 + ((x2b >> 2) << 1);
    const int prd  = (lane ^ (lane >> 2)) * 4;

    // resident Q fragments (already tf32-rounded + pre-scaled by mm epilogue)
    uint32_t Qf[8][4];
    {
        const uint32_t* Qu = (const uint32_t*)Qb;
        const int r0 = (q0 + qb + g) * 64;
#pragma unroll
        for (int ks = 0; ks < 8; ks++) {
            Qf[ks][0] = __ldg(&Qu[r0 + ks * 8 + t]);
            Qf[ks][1] = __ldg(&Qu[r0 + 512 + ks * 8 + t]);
            Qf[ks][2] = __ldg(&Qu[r0 + ks * 8 + t + 4]);
            Qf[ks][3] = __ldg(&Qu[r0 + 512 + ks * 8 + t + 4]);
        }
    }

    const int kvr = tid >> 4;
    const int kvc16 = tid & 15;

#define FL_ISSUE(buf, kv0n) do {                                               \
    _Pragma("unroll")                                                          \
    for (int _it = 0; _it < 4; _it++) {                                        \
        int _row = kvr + _it * 16;                                             \
        CP16(ksa[buf] + (uint32_t)((kvr + _it * 16) * 272 + kvc16 * 16),       \
             Kb + (size_t)((kv0n) + _row) * 64 + kvc16 * 4);                   \
        CP16(vsa[buf] + (uint32_t)((kvr + _it * 16) * 272 + kvc16 * 16),       \
             Vb + (size_t)_row * S_ + (kv0n) + kvc16 * 4);                     \
    }                                                                          \
    CP_COMMIT();                                                               \
} while (0)

    // prologue: KV tile 0
    FL_ISSUE(0, 0);

    float m_i[2] = { -1e30f, -1e30f }, l_i[2] = { 0.f, 0.f };
    float accO[8][4];
#pragma unroll
    for (int ni = 0; ni < 8; ni++)
#pragma unroll
        for (int r = 0; r < 4; r++) accO[ni][r] = 0.f;

    const int ntiles = 2 * qt + 2;
    for (int kt = 0; kt < ntiles; kt++) {
        const int cur = kt & 1;
        CP_WAIT0();          // KV tile kt arrived
        __syncthreads();     // all warps done with buffer cur^1 (iter kt-1)
        if (kt + 1 < ntiles)
            FL_ISSUE(cur ^ 1, (kt + 1) * 64);   // overlaps compute below

        // S = Q K^T  (warp: 16 x 64): K b-frags via ldmatrix (2 ni per x4)
        float sf[8][4];
#pragma unroll
        for (int ni = 0; ni < 8; ni++)
#pragma unroll
            for (int r = 0; r < 4; r++) sf[ni][r] = 0.f;

        const uint32_t kfb = ksa[cur] + laneKV;
#pragma unroll
        for (int ks = 0; ks < 8; ks++) {
#pragma unroll
            for (int nn = 0; nn < 8; nn += 2) {
                uint32_t bf[4];
                LDSM4(bf[0], bf[1], bf[2], bf[3], kfb + (uint32_t)(nn * 2176 + ks * 32));
                mma8(sf[nn],     Qf[ks], bf);
                mma8(sf[nn + 1], Qf[ks], bf + 2);
            }
        }

        if (kt >= 2 * qt) {  // diagonal region: causal mask
            const int kv0 = kt * 64;
            const int qr0 = q0 + qb + g, qr1 = qr0 + 8;
#pragma unroll
            for (int ni = 0; ni < 8; ni++) {
                int c0 = kv0 + ni * 8 + 2 * t;
                if (c0     > qr0) sf[ni][0] = -1e30f;
                if (c0 + 1 > qr0) sf[ni][1] = -1e30f;
                if (c0     > qr1) sf[ni][2] = -1e30f;
                if (c0 + 1 > qr1) sf[ni][3] = -1e30f;
            }
        }

        // online softmax in log2 domain (Q pre-scaled by log2e/8).
        // P left as raw fp32 — HMMA tf32 truncates low bits in HW.
#pragma unroll
        for (int rh = 0; rh < 2; rh++) {
            float mx = -1e30f;
#pragma unroll
            for (int ni = 0; ni < 8; ni++)
                mx = fmaxf(mx, fmaxf(sf[ni][rh * 2], sf[ni][rh * 2 + 1]));
            mx = fmaxf(mx, __shfl_xor_sync(0xffffffffu, mx, 1));
            mx = fmaxf(mx, __shfl_xor_sync(0xffffffffu, mx, 2));
            float mnew = fmaxf(m_i[rh], mx);
            float corr = exp2f(m_i[rh] - mnew);
            m_i[rh] = mnew;
            float sum = 0.f;
#pragma unroll
            for (int ni = 0; ni < 8; ni++) {
                float p0 = exp2f(sf[ni][rh * 2] - mnew);
                float p1 = exp2f(sf[ni][rh * 2 + 1] - mnew);
                sum += p0 + p1;
                sf[ni][rh * 2]     = p0;
                sf[ni][rh * 2 + 1] = p1;
            }
            sum += __shfl_xor_sync(0xffffffffu, sum, 1);
            sum += __shfl_xor_sync(0xffffffffu, sum, 2);
            l_i[rh] = l_i[rh] * corr + sum;
#pragma unroll
            for (int ni = 0; ni < 8; ni++) {
                accO[ni][rh * 2]     *= corr;
                accO[ni][rh * 2 + 1] *= corr;
            }
        }

        // store P in A-fragment order (per-warp region, swizzled)
#pragma unroll
        for (int ni = 0; ni < 8; ni++) {
            Pfw[ni * 128 + offa]     = __float_as_uint(sf[ni][0]);
            Pfw[ni * 128 + offb]     = __float_as_uint(sf[ni][1]);
            Pfw[ni * 128 + offa + 1] = __float_as_uint(sf[ni][2]);
            Pfw[ni * 128 + offb + 1] = __float_as_uint(sf[ni][3]);
        }
        __syncwarp();

        // O += P V : P a-frags via LDS128, V b-frags via ldmatrix
        const uint32_t vfb = vsa[cur] + laneKV;
#pragma unroll
        for (int kj = 0; kj < 8; kj++) {
            uint4 pv = *(const uint4*)&Pfw[kj * 128 + prd];
            uint32_t pf[4] = { pv.x, pv.y, pv.z, pv.w };
#pragma unroll
            for (int nn = 0; nn < 8; nn += 2) {
                uint32_t vf[4];
                LDSM4(vf[0], vf[1], vf[2], vf[3], vfb + (uint32_t)(nn * 2176 + kj * 32));
                mma8(accO[nn],     pf, vf);
                mma8(accO[nn + 1], pf, vf + 2);
            }
        }
        // no end-of-loop barrier: next iteration's top barrier protects buffers
    }
#undef FL_ISSUE

    // write O -> g_X [b][q][h*64 + dv] (tf32-rounded: oproj consumes raw)
    const float inv0 = 1.f / l_i[0], inv1 = 1.f / l_i[1];
    const int q = q0 + qb + g;
    float* xb = g_X + ((size_t)b * S_ + q) * D_ + h * DK_;
#pragma unroll
    for (int ni = 0; ni < 8; ni++) {
        int dv = ni * 8 + 2 * t;
        *(float2*)(xb + dv) = make_float2(
            __uint_as_float(f2tf32(accO[ni][0] * inv0)),
            __uint_as_float(f2tf32(accO[ni][1] * inv0)));
        *(float2*)(xb + 8 * D_ + dv) = make_float2(
            __uint_as_float(f2tf32(accO[ni][2] * inv1)),
            __uint_as_float(f2tf32(accO[ni][3] * inv1)));
    }
}

// ---------------------------------------------------------------------------
extern "C" void kernel_launch(void* const* d_in, const int* in_sizes, int n_in,
                              void* d_out, int out_size)
{
    const float* emb = (const float*)d_in[0];
    const float* Wq  = (const float*)d_in[1];
    const float* Wk  = (const float*)d_in[2];
    const float* Wv  = (const float*)d_in[3];
    const float* Wo  = (const float*)d_in[4];
    const float* bo  = (const float*)d_in[5];
    float* out = (float*)d_out;

    cudaFuncSetAttribute(mm_kernel,
                         cudaFuncAttributeMaxDynamicSharedMemorySize, MM_SMEM_BYTES);
    cudaFuncSetAttribute(flash_kernel,
                         cudaFuncAttributeMaxDynamicSharedMemorySize, FL_SMEM_BYTES);

    cvt_kernel   <<<(B_*S_*D_)/(256*4), 256>>>(emb);
    wtrans_kernel<<<dim3(16, 16, 3), 256>>>(Wq, Wk, Wv);
    wot_kernel   <<<dim3(16, 16), 256>>>(Wo);
    mm_kernel    <<<dim3(64, 24), 256, MM_SMEM_BYTES>>>(nullptr, nullptr, 0);
    flash_kernel <<<dim3(S_/128, H_, B_), 256, FL_SMEM_BYTES>>>();
    mm_kernel    <<<dim3(64, 8), 256, MM_SMEM_BYTES>>>(bo, out, 1);
}

// round 16
// speedup vs baseline: 1.0054x; 1.0054x over previous
#include <cuda_runtime.h>
#include <cstdint>

#define B_  4
#define S_  2048
#define D_  1024
#define H_  16
#define DK_ 64

#define QKV_Z ((size_t)B_*H_*DK_*S_)   // floats per z-slab

// Scratch (device globals). MUST only be referenced from device code:
// host-side references give the host shadow address, which GB300 ATS
// silently dereferences (round-3/4 bug).
__device__ float g_QKV[3*QKV_Z];              // z0: Q [B,H,S,dk] (tf32, pre-scaled 0.125*log2e); z1: K [B,H,S,dk] (tf32); z2: V [B,H,dv,S] (tf32)
__device__ float g_X[(size_t)B_*S_*D_];       // concat-heads attention output (tf32-rounded)
__device__ float g_embT[(size_t)B_*S_*D_];    // emb pre-converted to tf32
__device__ float g_Wall[(size_t)3*H_*DK_*D_]; // [3072][1024] K-major fused QKV weights (tf32)
__device__ float g_Wot[(size_t)D_*D_];        // [1024][1024] K-major output weights (tf32)

// ============================ helpers ======================================
__device__ __forceinline__ uint32_t f2tf32(float x) {
    uint32_t u;
    asm("cvt.rna.tf32.f32 %0, %1;" : "=r"(u) : "f"(x));
    return u;
}
__device__ __forceinline__ void mma8(float* d, const uint32_t* a, const uint32_t* b) {
    asm volatile(
        "mma.sync.aligned.m16n8k8.row.col.f32.tf32.tf32.f32 "
        "{%0,%1,%2,%3}, {%4,%5,%6,%7}, {%8,%9}, {%0,%1,%2,%3};"
        : "+f"(d[0]), "+f"(d[1]), "+f"(d[2]), "+f"(d[3])
        : "r"(a[0]), "r"(a[1]), "r"(a[2]), "r"(a[3]), "r"(b[0]), "r"(b[1]));
}
__device__ __forceinline__ uint32_t smem_u32(const void* p) {
    uint32_t a;
    asm("{ .reg .u64 t; cvta.to.shared.u64 t, %1; cvt.u32.u64 %0, t; }"
        : "=r"(a) : "l"(p));
    return a;
}
#define CP16(d, s) \
    asm volatile("cp.async.cg.shared.global [%0], [%1], 16;" :: "r"(d), "l"(s))
#define CP_COMMIT() asm volatile("cp.async.commit_group;" ::: "memory")
#define CP_WAIT0()  asm volatile("cp.async.wait_group 0;" ::: "memory")
#define LDSM4(r0, r1, r2, r3, addr) \
    asm volatile("ldmatrix.sync.aligned.m8n8.x4.shared.b16 {%0,%1,%2,%3}, [%4];" \
        : "=r"(r0), "=r"(r1), "=r"(r2), "=r"(r3) : "r"(addr))

// ============== fused prep: cvt(emb) + wtrans(QKV) + wot ==================
// blockIdx.x: [0, 8192)           -> emb fp32 -> tf32 (1024 elems/block)
//             [8192, 8192+768)    -> QKV weight transpose (dt, h, z)
//             [8960, 8960+256)    -> Wo transpose (kt, nt)
#define PREP_CVT_BLOCKS  8192
#define PREP_WT_BLOCKS   768
#define PREP_WOT_BLOCKS  256
#define PREP_BLOCKS (PREP_CVT_BLOCKS + PREP_WT_BLOCKS + PREP_WOT_BLOCKS)

__global__ __launch_bounds__(256) void prep_kernel(
    const float* __restrict__ emb,
    const float* __restrict__ Wq, const float* __restrict__ Wk,
    const float* __restrict__ Wv, const float* __restrict__ Wo)
{
    __shared__ float t[64][65];
    const int bx = blockIdx.x;

    if (bx < PREP_CVT_BLOCKS) {
        size_t i = ((size_t)bx * 256 + threadIdx.x) * 4;
        float4 v = __ldg((const float4*)(emb + i));
        uint4 o = make_uint4(f2tf32(v.x), f2tf32(v.y), f2tf32(v.z), f2tf32(v.w));
        *(uint4*)((uint32_t*)g_embT + i) = o;
        return;
    }

    if (bx < PREP_CVT_BLOCKS + PREP_WT_BLOCKS) {
        const int id = bx - PREP_CVT_BLOCKS;       // 768 = 16 dt x 16 h x 3 z
        const int dt = id & 15, h = (id >> 4) & 15, z = id >> 8;
        const float* W = (z == 0 ? Wq : (z == 1 ? Wk : Wv)) + (size_t)h * D_ * DK_;
        const int d0 = dt * 64;
#pragma unroll
        for (int i = 0; i < 16; i++) {
            int idx = threadIdx.x + i * 256;
            int r = idx >> 6, c = idx & 63;
            t[c][r] = W[(size_t)(d0 + r) * DK_ + c];
        }
        __syncthreads();
#pragma unroll
        for (int i = 0; i < 16; i++) {
            int idx = threadIdx.x + i * 256;
            int r = idx >> 6, c = idx & 63;
            g_Wall[(size_t)(z * 1024 + h * 64 + r) * D_ + d0 + c] =
                __uint_as_float(f2tf32(t[r][c]));
        }
        return;
    }

    {
        const int id = bx - PREP_CVT_BLOCKS - PREP_WT_BLOCKS;  // 256 = 16 kt x 16 nt
        const int kt = id & 15, nt = id >> 4;
        const int k0 = kt * 64, n0 = nt * 64;
#pragma unroll
        for (int i = 0; i < 16; i++) {
            int idx = threadIdx.x + i * 256;
            int r = idx >> 6, c = idx & 63;
            t[c][r] = Wo[(size_t)(k0 + r) * D_ + n0 + c];
        }
        __syncthreads();
#pragma unroll
        for (int i = 0; i < 16; i++) {
            int idx = threadIdx.x + i * 256;
            int r = idx >> 6, c = idx & 63;
            g_Wot[(size_t)(n0 + r) * D_ + k0 + c] = __uint_as_float(f2tf32(t[r][c]));
        }
    }
}

// =============== HMMA tf32 GEMM: C[M,N] = A[M,K] * B[N,K]^T ================
// Both operands pre-converted tf32 in gmem -> raw cp.async; fragments via
// ldmatrix.x4. 128x128 CTA tile, 8 warps 4(M)x2(N), KC=32, double buffered.
// Single barrier per chunk (wait c -> sync -> issue c+1 -> compute c).
// __launch_bounds__(256,2): cap regs at 128 so 2 CTAs/SM fit.
#define MMLDA 36
#define MM_SMEM_BYTES 73728

__global__ __launch_bounds__(256, 2) void mm_kernel(
    const float* __restrict__ bias, float* __restrict__ Cout, int mode)
{
    extern __shared__ __align__(16) uint32_t smu[];
    const uint32_t sb = smem_u32(smu);
    const uint32_t Asa[2] = { sb,               sb + 9216u * 4u };
    const uint32_t Bofs = 4608u * 4u;

    const float* A  = (mode == 0) ? g_embT : g_X;
    const float* Bm = (mode == 0) ? g_Wall : g_Wot;

    const int tid = threadIdx.x;
    const int m0 = blockIdx.x * 128, n0 = blockIdx.y * 128;
    const int w = tid >> 5, lane = tid & 31;
    const int wm = w & 3, wn = w >> 2;
    const int g = lane >> 2, t = lane & 3;

    float acc[2][8][4];
#pragma unroll
    for (int mi = 0; mi < 2; mi++)
#pragma unroll
        for (int ni = 0; ni < 8; ni++)
#pragma unroll
            for (int r = 0; r < 4; r++) acc[mi][ni][r] = 0.f;

    const int ldr = tid >> 3, ldc = tid & 7;
    const uint32_t dsto = (uint32_t)(ldr * MMLDA + ldc * 4) * 4u;

    const uint32_t laneA = (uint32_t)((((lane & 7) + ((lane >> 3) & 1) * 8) * MMLDA
                                       + ((lane >> 4) & 1) * 4) * 4);
    const uint32_t laneB = (uint32_t)(((((lane >> 4) & 1) * 8 + (lane & 7)) * MMLDA
                                       + ((lane >> 3) & 1) * 4) * 4);

#define MM_ISSUE(stagebase, k0n) do {                                          \
    _Pragma("unroll")                                                          \
    for (int _i = 0; _i < 4; _i++) {                                           \
        CP16((stagebase) + dsto + (uint32_t)(_i * 32 * MMLDA * 4),             \
             A  + (size_t)(m0 + ldr + _i * 32) * D_ + (k0n) + ldc * 4);        \
        CP16((stagebase) + Bofs + dsto + (uint32_t)(_i * 32 * MMLDA * 4),      \
             Bm + (size_t)(n0 + ldr + _i * 32) * D_ + (k0n) + ldc * 4);        \
    }                                                                          \
    CP_COMMIT();                                                               \
} while (0)

    MM_ISSUE(Asa[0], 0);

    for (int c = 0; c < 32; c++) {
        const int cur = c & 1;
        CP_WAIT0();
        __syncthreads();
        if (c + 1 < 32)
            MM_ISSUE(Asa[cur ^ 1], (c + 1) * 32);
        const uint32_t abase = Asa[cur] + laneA + (uint32_t)(wm * 32 * MMLDA * 4);
        const uint32_t bbase = Asa[cur] + Bofs + laneB + (uint32_t)(wn * 64 * MMLDA * 4);
#pragma unroll
        for (int ks = 0; ks < 4; ks++) {
            uint32_t a0[4], a1[4];
            LDSM4(a0[0], a0[1], a0[2], a0[3], abase + (uint32_t)(ks * 32));
            LDSM4(a1[0], a1[1], a1[2], a1[3],
                  abase + (uint32_t)(16 * MMLDA * 4 + ks * 32));
#pragma unroll
            for (int nn = 0; nn < 8; nn += 2) {
                uint32_t bf[4];
                LDSM4(bf[0], bf[1], bf[2], bf[3],
                      bbase + (uint32_t)(nn * 8 * MMLDA * 4 + ks * 32));
                mma8(acc[0][nn],     a0, bf);
                mma8(acc[0][nn + 1], a0, bf + 2);
                mma8(acc[1][nn],     a1, bf);
                mma8(acc[1][nn + 1], a1, bf + 2);
            }
        }
    }
#undef MM_ISSUE
    __syncthreads();   // protect epilogue smem reuse (mode 0, z==2)

    // ---------------- epilogue ----------------
    if (mode == 0) {
        const int z = n0 >> 10;
        const int bidx = m0 >> 11, s0 = m0 & 2047;
        if (z == 2) {
            float* smf = (float*)smu;           // [col][row], ld=132
#pragma unroll
            for (int mi = 0; mi < 2; mi++)
#pragma unroll
                for (int ni = 0; ni < 8; ni++) {
                    int r = wm * 32 + mi * 16 + g;
                    int cc = wn * 64 + ni * 8 + 2 * t;
                    smf[cc * 132 + r]           = acc[mi][ni][0];
                    smf[(cc + 1) * 132 + r]     = acc[mi][ni][1];
                    smf[cc * 132 + r + 8]       = acc[mi][ni][2];
                    smf[(cc + 1) * 132 + r + 8] = acc[mi][ni][3];
                }
            __syncthreads();
            float* vbase = g_QKV + 2 * QKV_Z;
#pragma unroll
            for (int ccc = 0; ccc < 16; ccc++) {
                int col = w + ccc * 8;
                int nglob = n0 + col;
                int h = (nglob >> 6) & 15, kb = nglob & 63;
                float* dst = vbase + ((size_t)(bidx * 16 + h) * 64 + kb) * 2048 + s0;
#pragma unroll
                for (int rr = 0; rr < 4; rr++)
                    dst[rr * 32 + lane] =
                        __uint_as_float(f2tf32(smf[col * 132 + rr * 32 + lane]));
            }
        } else {
            const float qsc = (z == 0) ? 0.125f * 1.4426950408889634f : 1.0f;
            float* zbase = g_QKV + (size_t)z * QKV_Z;
#pragma unroll
            for (int mi = 0; mi < 2; mi++)
#pragma unroll
                for (int ni = 0; ni < 8; ni++) {
                    int r = m0 + wm * 32 + mi * 16 + g;
                    int s = r & 2047;
                    int n = n0 + wn * 64 + ni * 8 + 2 * t;
                    int h = (n >> 6) & 15, kb = n & 63;
                    float* dst = zbase + ((size_t)(bidx * 16 + h) * 2048 + s) * 64 + kb;
                    *(float2*)dst = make_float2(
                        __uint_as_float(f2tf32(qsc * acc[mi][ni][0])),
                        __uint_as_float(f2tf32(qsc * acc[mi][ni][1])));
                    *(float2*)(dst + 8 * 64) = make_float2(
                        __uint_as_float(f2tf32(qsc * acc[mi][ni][2])),
                        __uint_as_float(f2tf32(qsc * acc[mi][ni][3])));
                }
        }
    } else {
#pragma unroll
        for (int mi = 0; mi < 2; mi++)
#pragma unroll
            for (int ni = 0; ni < 8; ni++) {
                int m = m0 + wm * 32 + mi * 16 + g;
                int n = n0 + wn * 64 + ni * 8 + 2 * t;
                float2 bv = *(const float2*)(bias + n);
                *(float2*)(Cout + (size_t)m * D_ + n) =
                    make_float2(acc[mi][ni][0] + bv.x, acc[mi][ni][1] + bv.y);
                *(float2*)(Cout + (size_t)(m + 8) * D_ + n) =
                    make_float2(acc[mi][ni][2] + bv.x, acc[mi][ni][3] + bv.y);
            }
    }
}

// ================ Flash attention on HMMA tf32, causal =====================
// BQ=128, BK=64, 256 threads; warp wq owns q-rows [wq*16, wq*16+16).
// Q resident in registers; K smem [kv][dk], V smem [dv][kv] (ld=68,
// LDSM-conflict-free); B-frags via ldmatrix.x4; P through per-warp smem.
// SINGLE __syncthreads per tile (round-14 structure).
#define FL_KS0b 0
#define FL_KS1b 17408
#define FL_VS0b 34816
#define FL_VS1b 52224
#define FL_Pb   69632
#define FL_SMEM_BYTES 102400

__global__ __launch_bounds__(256, 2) void flash_kernel()
{
    extern __shared__ __align__(16) uint32_t smu[];
    const uint32_t sb = smem_u32(smu);
    const uint32_t ksa[2] = { sb + FL_KS0b, sb + FL_KS1b };
    const uint32_t vsa[2] = { sb + FL_VS0b, sb + FL_VS1b };

    const int qt = (int)gridDim.x - 1 - (int)blockIdx.x;  // heavy tiles first
    const int h = blockIdx.y, b = blockIdx.z;
    const int bh = b * H_ + h;
    const float* Qb = g_QKV + (size_t)bh * S_ * 64;             // [S][dk]
    const float* Kb = g_QKV + QKV_Z + (size_t)bh * S_ * 64;     // [S][dk]
    const float* Vb = g_QKV + 2 * QKV_Z + (size_t)bh * 64 * S_; // [dv][S]
    const int q0 = qt * 128;
    const int tid = threadIdx.x;
    const int wq = tid >> 5, lane = tid & 31;
    const int g = lane >> 2, t = lane & 3;
    const int qb = wq * 16;

    const int lrow8 = lane & 7;
    const int lsel  = ((lane >> 3) & 1) * 4;
    const int lblk  = (lane >> 4) & 1;
    const uint32_t laneKV = (uint32_t)(((lblk * 8 + lrow8) * 68 + lsel) * 4);

    uint32_t* Pfw = smu + FL_Pb / 4 + wq * 1024;
    const int x2a = 2 * t, x2b = 2 * t + 1;
    const int l2a = 4 * g + (x2a & 3), l2b = 4 * g + (x2b & 3);
    const int offa = (l2a ^ (l2a >> 2)) * 4 + ((x2a >> 2) << 1);
    const int offb = (l2b ^ (l2b >> 2)) * 4 + ((x2b >> 2) << 1);
    const int prd  = (lane ^ (lane >> 2)) * 4;

    uint32_t Qf[8][4];
    {
        const uint32_t* Qu = (const uint32_t*)Qb;
        const int r0 = (q0 + qb + g) * 64;
#pragma unroll
        for (int ks = 0; ks < 8; ks++) {
            Qf[ks][0] = __ldg(&Qu[r0 + ks * 8 + t]);
            Qf[ks][1] = __ldg(&Qu[r0 + 512 + ks * 8 + t]);
            Qf[ks][2] = __ldg(&Qu[r0 + ks * 8 + t + 4]);
            Qf[ks][3] = __ldg(&Qu[r0 + 512 + ks * 8 + t + 4]);
        }
    }

    const int kvr = tid >> 4;
    const int kvc16 = tid & 15;

#define FL_ISSUE(buf, kv0n) do {                                               \
    _Pragma("unroll")                                                          \
    for (int _it = 0; _it < 4; _it++) {                                        \
        int _row = kvr + _it * 16;                                             \
        CP16(ksa[buf] + (uint32_t)((kvr + _it * 16) * 272 + kvc16 * 16),       \
             Kb + (size_t)((kv0n) + _row) * 64 + kvc16 * 4);                   \
        CP16(vsa[buf] + (uint32_t)((kvr + _it * 16) * 272 + kvc16 * 16),       \
             Vb + (size_t)_row * S_ + (kv0n) + kvc16 * 4);                     \
    }                                                                          \
    CP_COMMIT();                                                               \
} while (0)

    FL_ISSUE(0, 0);

    float m_i[2] = { -1e30f, -1e30f }, l_i[2] = { 0.f, 0.f };
    float accO[8][4];
#pragma unroll
    for (int ni = 0; ni < 8; ni++)
#pragma unroll
        for (int r = 0; r < 4; r++) accO[ni][r] = 0.f;

    const int ntiles = 2 * qt + 2;
    for (int kt = 0; kt < ntiles; kt++) {
        const int cur = kt & 1;
        CP_WAIT0();
        __syncthreads();
        if (kt + 1 < ntiles)
            FL_ISSUE(cur ^ 1, (kt + 1) * 64);

        float sf[8][4];
#pragma unroll
        for (int ni = 0; ni < 8; ni++)
#pragma unroll
            for (int r = 0; r < 4; r++) sf[ni][r] = 0.f;

        const uint32_t kfb = ksa[cur] + laneKV;
#pragma unroll
        for (int ks = 0; ks < 8; ks++) {
#pragma unroll
            for (int nn = 0; nn < 8; nn += 2) {
                uint32_t bf[4];
                LDSM4(bf[0], bf[1], bf[2], bf[3], kfb + (uint32_t)(nn * 2176 + ks * 32));
                mma8(sf[nn],     Qf[ks], bf);
                mma8(sf[nn + 1], Qf[ks], bf + 2);
            }
        }

        if (kt >= 2 * qt) {
            const int kv0 = kt * 64;
            const int qr0 = q0 + qb + g, qr1 = qr0 + 8;
#pragma unroll
            for (int ni = 0; ni < 8; ni++) {
                int c0 = kv0 + ni * 8 + 2 * t;
                if (c0     > qr0) sf[ni][0] = -1e30f;
                if (c0 + 1 > qr0) sf[ni][1] = -1e30f;
                if (c0     > qr1) sf[ni][2] = -1e30f;
                if (c0 + 1 > qr1) sf[ni][3] = -1e30f;
            }
        }

#pragma unroll
        for (int rh = 0; rh < 2; rh++) {
            float mx = -1e30f;
#pragma unroll
            for (int ni = 0; ni < 8; ni++)
                mx = fmaxf(mx, fmaxf(sf[ni][rh * 2], sf[ni][rh * 2 + 1]));
            mx = fmaxf(mx, __shfl_xor_sync(0xffffffffu, mx, 1));
            mx = fmaxf(mx, __shfl_xor_sync(0xffffffffu, mx, 2));
            float mnew = fmaxf(m_i[rh], mx);
            float corr = exp2f(m_i[rh] - mnew);
            m_i[rh] = mnew;
            float sum = 0.f;
#pragma unroll
            for (int ni = 0; ni < 8; ni++) {
                float p0 = exp2f(sf[ni][rh * 2] - mnew);
                float p1 = exp2f(sf[ni][rh * 2 + 1] - mnew);
                sum += p0 + p1;
                sf[ni][rh * 2]     = p0;
                sf[ni][rh * 2 + 1] = p1;
            }
            sum += __shfl_xor_sync(0xffffffffu, sum, 1);
            sum += __shfl_xor_sync(0xffffffffu, sum, 2);
            l_i[rh] = l_i[rh] * corr + sum;
#pragma unroll
            for (int ni = 0; ni < 8; ni++) {
                accO[ni][rh * 2]     *= corr;
                accO[ni][rh * 2 + 1] *= corr;
            }
        }

#pragma unroll
        for (int ni = 0; ni < 8; ni++) {
            Pfw[ni * 128 + offa]     = __float_as_uint(sf[ni][0]);
            Pfw[ni * 128 + offb]     = __float_as_uint(sf[ni][1]);
            Pfw[ni * 128 + offa + 1] = __float_as_uint(sf[ni][2]);
            Pfw[ni * 128 + offb + 1] = __float_as_uint(sf[ni][3]);
        }
        __syncwarp();

        const uint32_t vfb = vsa[cur] + laneKV;
#pragma unroll
        for (int kj = 0; kj < 8; kj++) {
            uint4 pv = *(const uint4*)&Pfw[kj * 128 + prd];
            uint32_t pf[4] = { pv.x, pv.y, pv.z, pv.w };
#pragma unroll
            for (int nn = 0; nn < 8; nn += 2) {
                uint32_t vf[4];
                LDSM4(vf[0], vf[1], vf[2], vf[3], vfb + (uint32_t)(nn * 2176 + kj * 32));
                mma8(accO[nn],     pf, vf);
                mma8(accO[nn + 1], pf, vf + 2);
            }
        }
    }
#undef FL_ISSUE

    const float inv0 = 1.f / l_i[0], inv1 = 1.f / l_i[1];
    const int q = q0 + qb + g;
    float* xb = g_X + ((size_t)b * S_ + q) * D_ + h * DK_;
#pragma unroll
    for (int ni = 0; ni < 8; ni++) {
        int dv = ni * 8 + 2 * t;
        *(float2*)(xb + dv) = make_float2(
            __uint_as_float(f2tf32(accO[ni][0] * inv0)),
            __uint_as_float(f2tf32(accO[ni][1] * inv0)));
        *(float2*)(xb + 8 * D_ + dv) = make_float2(
            __uint_as_float(f2tf32(accO[ni][2] * inv1)),
            __uint_as_float(f2tf32(accO[ni][3] * inv1)));
    }
}

// ---------------------------------------------------------------------------
extern "C" void kernel_launch(void* const* d_in, const int* in_sizes, int n_in,
                              void* d_out, int out_size)
{
    const float* emb = (const float*)d_in[0];
    const float* Wq  = (const float*)d_in[1];
    const float* Wk  = (const float*)d_in[2];
    const float* Wv  = (const float*)d_in[3];
    const float* Wo  = (const float*)d_in[4];
    const float* bo  = (const float*)d_in[5];
    float* out = (float*)d_out;

    cudaFuncSetAttribute(mm_kernel,
                         cudaFuncAttributeMaxDynamicSharedMemorySize, MM_SMEM_BYTES);
    cudaFuncSetAttribute(flash_kernel,
                         cudaFuncAttributeMaxDynamicSharedMemorySize, FL_SMEM_BYTES);

    prep_kernel  <<<PREP_BLOCKS, 256>>>(emb, Wq, Wk, Wv, Wo);
    mm_kernel    <<<dim3(64, 24), 256, MM_SMEM_BYTES>>>(nullptr, nullptr, 0);
    flash_kernel <<<dim3(S_/128, H_, B_), 256, FL_SMEM_BYTES>>>();
    mm_kernel    <<<dim3(64, 8), 256, MM_SMEM_BYTES>>>(bo, out, 1);
}